// round 13
// baseline (speedup 1.0000x reference)
#include <cuda_runtime.h>
#include <cuda_fp16.h>
#include <cstdint>

#define N_NODES  50000
#define N_EDGES  800000
#define N_GRAPHS 64
#define D_IN     128
#define D_H      256
#define SLOT     64                       // fixed CSR capacity per node

// ==================== scratch (no allocations allowed) ====================
__device__ __half g_x16[(size_t)N_NODES * D_IN];
__device__ __half g_a16[(size_t)N_NODES * D_H];
__device__ __half g_t16[(size_t)N_NODES * D_H];
__device__ __half g_h16[(size_t)N_NODES * D_H];
__device__ __half g_wh[4][D_H * D_H];
__device__ int g_cursor[N_NODES];
__device__ int g_csr[(size_t)N_NODES * SLOT];
__device__ float g_sums[N_GRAPHS * D_H];
__device__ float g_counts[N_GRAPHS];

__device__ __forceinline__ uint32_t smem_u32(const void* p) {
    uint32_t a;
    asm("{ .reg .u64 t; cvta.to.shared.u64 t, %1; cvt.u32.u64 %0, t; }"
        : "=r"(a) : "l"(p));
    return a;
}

// ==================== mega init: cvt x + prep weights + cursor + pool zero ====================
__global__ void init_kernel(const float4* __restrict__ x, uint2* __restrict__ x16,
                            const float* __restrict__ W0, const float* __restrict__ W1,
                            const float* __restrict__ W2, const float* __restrict__ W3,
                            __half* __restrict__ wh,
                            int* __restrict__ cursor,
                            float* __restrict__ sums, float* __restrict__ counts) {
    int i = blockIdx.x * blockDim.x + threadIdx.x;

    if (i < N_NODES * D_IN / 4) {
        float4 v = x[i];
        __half2 a = __floats2half2_rn(v.x, v.y);
        __half2 b = __floats2half2_rn(v.z, v.w);
        x16[i] = make_uint2(*(uint32_t*)&a, *(uint32_t*)&b);
    }
    if (i < 128 * 256 + 3 * 65536) {
        const float* W; int K; size_t base; int local;
        if (i < 128 * 256)              { W = W0; K = 128; base = 0;                     local = i; }
        else if (i < 128 * 256 + 65536) { W = W1; K = 256; base = (size_t)D_H * D_H;     local = i - 128 * 256; }
        else if (i < 128 * 256 + 131072){ W = W2; K = 256; base = (size_t)2 * D_H * D_H; local = i - 128 * 256 - 65536; }
        else                            { W = W3; K = 256; base = (size_t)3 * D_H * D_H; local = i - 128 * 256 - 131072; }
        int k = local / 256, n = local % 256;
        wh[base + (size_t)n * K + k] = __float2half_rn(W[(size_t)k * 256 + n]);
    }
    if (i < N_NODES) cursor[i] = i * SLOT;
    if (i < N_GRAPHS * D_H) sums[i] = 0.f;
    else if (i < N_GRAPHS * D_H + N_GRAPHS) counts[i - N_GRAPHS * D_H] = 0.f;
}

// ==================== slotted CSR fill ====================
__global__ void fill_kernel(const int* __restrict__ ei, int* __restrict__ cursor,
                            int* __restrict__ csr) {
    int e = blockIdx.x * blockDim.x + threadIdx.x;
    if (e < N_EDGES) {
        int pos = atomicAdd(&cursor[ei[N_EDGES + e]], 1);
        csr[pos] = ei[e];
    }
}

// ==================== fp16 gather: A[n] = X[n] + sum_{s in slot(n)} X[s] ====================
template <int F>
__global__ void gather_f16(const __half* __restrict__ X,
                           const int* __restrict__ cursor,
                           const int* __restrict__ csr,
                           __half* __restrict__ A) {
    int warp = (blockIdx.x * blockDim.x + threadIdx.x) >> 5;
    int lane = threadIdx.x & 31;
    if (warp >= N_NODES) return;
    constexpr int C = F / 128;
    float acc[C][4];
    const uint2* xs = (const uint2*)(X + (size_t)warp * F);
    #pragma unroll
    for (int c = 0; c < C; c++) {
        uint2 v = xs[lane + c * 32];
        float2 f0 = __half22float2(*(__half2*)&v.x);
        float2 f1 = __half22float2(*(__half2*)&v.y);
        acc[c][0] = f0.x; acc[c][1] = f0.y; acc[c][2] = f1.x; acc[c][3] = f1.y;
    }
    int beg = warp * SLOT, end = cursor[warp];
    for (int e = beg; e < end; e++) {
        const uint2* r = (const uint2*)(X + (size_t)csr[e] * F);
        #pragma unroll
        for (int c = 0; c < C; c++) {
            uint2 v = r[lane + c * 32];
            float2 f0 = __half22float2(*(__half2*)&v.x);
            float2 f1 = __half22float2(*(__half2*)&v.y);
            acc[c][0] += f0.x; acc[c][1] += f0.y; acc[c][2] += f1.x; acc[c][3] += f1.y;
        }
    }
    uint2* out = (uint2*)(A + (size_t)warp * F);
    #pragma unroll
    for (int c = 0; c < C; c++) {
        __half2 o0 = __floats2half2_rn(acc[c][0], acc[c][1]);
        __half2 o1 = __floats2half2_rn(acc[c][2], acc[c][3]);
        out[lane + c * 32] = make_uint2(*(uint32_t*)&o0, *(uint32_t*)&o1);
    }
}

// ==================== 3-stage cp.async fp16 mma GEMM with ldmatrix ====================
// C = relu(A @ B^T + bias).  Block 128x128, 8 warps (4m x 2n), warp 32x64, BK=64.
#define GSW 72
#define TILE_B  (128 * GSW * 2)               // 18432 B
#define STAGE_B (2 * TILE_B)                  // A | B  (36864)
#define N_STAGE 3
#define GEMM_SMEM (N_STAGE * STAGE_B)         // 110592

__device__ __forceinline__ void mma_f16(float* d, const uint32_t* a, const uint32_t* b) {
    asm volatile(
        "mma.sync.aligned.m16n8k16.row.col.f32.f16.f16.f32 "
        "{%0,%1,%2,%3}, {%4,%5,%6,%7}, {%8,%9}, {%0,%1,%2,%3};"
        : "+f"(d[0]), "+f"(d[1]), "+f"(d[2]), "+f"(d[3])
        : "r"(a[0]), "r"(a[1]), "r"(a[2]), "r"(a[3]), "r"(b[0]), "r"(b[1]));
}
__device__ __forceinline__ void cp16(uint32_t dst, const void* src, int srcsize) {
    asm volatile("cp.async.cg.shared.global [%0], [%1], 16, %2;"
                 :: "r"(dst), "l"(src), "r"(srcsize) : "memory");
}
__device__ __forceinline__ void ldsm_x4(uint32_t& r0, uint32_t& r1, uint32_t& r2,
                                        uint32_t& r3, uint32_t addr) {
    asm volatile("ldmatrix.sync.aligned.m8n8.x4.shared.b16 {%0,%1,%2,%3}, [%4];"
                 : "=r"(r0), "=r"(r1), "=r"(r2), "=r"(r3) : "r"(addr));
}

__global__ void __launch_bounds__(256, 2)
gemm_f16(const __half* __restrict__ Ag, const __half* __restrict__ BT,
         const float* __restrict__ bias,
         __half* __restrict__ O, int M, int K) {
    extern __shared__ char smem_raw[];
    const uint32_t sb = smem_u32(smem_raw);

    const int tid  = threadIdx.x;
    const int wid  = tid >> 5;
    const int lane = tid & 31;
    const int m0   = blockIdx.x * 128;
    const int n0   = blockIdx.y * 128;
    const int wm   = (wid & 3) * 32;
    const int wn   = (wid >> 2) * 64;
    const int fr   = lane >> 2;
    const int fc   = (lane & 3) * 2;
    const int lm16 = lane & 15;          // ldmatrix row within 16-row tile
    const int lh   = lane >> 4;          // ldmatrix k-half selector

    const int lrow[4] = { (tid + 0)   >> 3, (tid + 256) >> 3,
                          (tid + 512) >> 3, (tid + 768) >> 3 };
    const int lq = tid & 7;

    // ldmatrix byte offsets within a stage (kk added per step)
    const uint32_t offA0 = (uint32_t)((wm + lm16)      * GSW + lh * 8) * 2;
    const uint32_t offA1 = (uint32_t)((wm + 16 + lm16) * GSW + lh * 8) * 2;
    const uint32_t offB0 = (uint32_t)((wn + lm16)      * GSW + lh * 8) * 2 + TILE_B;
    // B pairs p=0..3 cover n rows wn+16p .. wn+16p+15

    float acc[2][8][4];
    #pragma unroll
    for (int a = 0; a < 2; a++)
        #pragma unroll
        for (int b = 0; b < 8; b++)
            #pragma unroll
            for (int c = 0; c < 4; c++) acc[a][b][c] = 0.f;

    const int niter = K >> 6;

    auto issue = [&](int it) {
        const uint32_t sab = sb + (it % N_STAGE) * STAGE_B;
        const int k0 = it * 64;
        #pragma unroll
        for (int t = 0; t < 4; t++) {
            int row = lrow[t];
            uint32_t so = (uint32_t)(row * GSW + lq * 8) * 2;
            int gm = m0 + row;
            int pm = (gm < M) ? 16 : 0;
            int gma = (gm < M) ? gm : 0;
            cp16(sab + 0 * TILE_B + so, Ag + (size_t)gma * K + k0 + lq * 8, pm);
            cp16(sab + 1 * TILE_B + so, BT + (size_t)(n0 + row) * K + k0 + lq * 8, 16);
        }
        asm volatile("cp.async.commit_group;" ::: "memory");
    };

    issue(0);
    if (niter > 1) issue(1);
    for (int it = 0; it < niter; it++) {
        if (it + 2 < niter) {
            issue(it + 2);
            asm volatile("cp.async.wait_group 2;" ::: "memory");
        } else if (it + 1 < niter) {
            asm volatile("cp.async.wait_group 1;" ::: "memory");
        } else {
            asm volatile("cp.async.wait_group 0;" ::: "memory");
        }
        __syncthreads();

        const uint32_t sstage = sb + (it % N_STAGE) * STAGE_B;

        #pragma unroll
        for (int kk = 0; kk < 64; kk += 16) {
            const uint32_t kkb = (uint32_t)kk * 2;
            uint32_t af[2][4];
            ldsm_x4(af[0][0], af[0][1], af[0][2], af[0][3], sstage + offA0 + kkb);
            ldsm_x4(af[1][0], af[1][1], af[1][2], af[1][3], sstage + offA1 + kkb);

            uint32_t bf[8][2];
            #pragma unroll
            for (int p = 0; p < 4; p++) {
                uint32_t r0, r1, r2, r3;
                ldsm_x4(r0, r1, r2, r3,
                        sstage + offB0 + (uint32_t)(p * 16 * GSW) * 2 + kkb);
                bf[2 * p][0]     = r0;
                bf[2 * p + 1][0] = r1;
                bf[2 * p][1]     = r2;
                bf[2 * p + 1][1] = r3;
            }
            #pragma unroll
            for (int nt = 0; nt < 8; nt++)
                #pragma unroll
                for (int mt = 0; mt < 2; mt++)
                    mma_f16(acc[mt][nt], af[mt], bf[nt]);
        }
        __syncthreads();
    }

    // ---- epilogue: bias + relu -> fp16 ----
    #pragma unroll
    for (int mt = 0; mt < 2; mt++) {
        int gr0 = m0 + wm + mt * 16 + fr;
        int gr1 = gr0 + 8;
        #pragma unroll
        for (int nt = 0; nt < 8; nt++) {
            int col = n0 + wn + nt * 8 + fc;
            float b0 = bias[col], b1 = bias[col + 1];
            if (gr0 < M) {
                __half2 p = __floats2half2_rn(fmaxf(acc[mt][nt][0] + b0, 0.f),
                                              fmaxf(acc[mt][nt][1] + b1, 0.f));
                *(__half2*)(O + (size_t)gr0 * 256 + col) = p;
            }
            if (gr1 < M) {
                __half2 p = __floats2half2_rn(fmaxf(acc[mt][nt][2] + b0, 0.f),
                                              fmaxf(acc[mt][nt][3] + b1, 0.f));
                *(__half2*)(O + (size_t)gr1 * 256 + col) = p;
            }
        }
    }
}

// ==================== pool (fp16 in, fp32 out) ====================
#define POOL_NPB 128
__global__ void pool_kernel(const __half* __restrict__ H,
                            const int* __restrict__ batch,
                            float* __restrict__ sums, float* __restrict__ counts) {
    int f  = threadIdx.x;
    int n0 = blockIdx.x * POOL_NPB;
    int n1 = n0 + POOL_NPB;
    if (n1 > N_NODES) n1 = N_NODES;
    if (n0 >= N_NODES) return;

    float acc = 0.f;
    int cur = batch[n0];
    int runstart = n0;
    for (int n = n0; n < n1; n++) {
        int g = batch[n];
        if (g != cur) {
            atomicAdd(&sums[cur * D_H + f], acc);
            if (f == 0) atomicAdd(&counts[cur], (float)(n - runstart));
            acc = 0.f; cur = g; runstart = n;
        }
        acc += __half2float(H[(size_t)n * D_H + f]);
    }
    atomicAdd(&sums[cur * D_H + f], acc);
    if (f == 0) atomicAdd(&counts[cur], (float)(n1 - runstart));
}

__global__ void div_kernel(const float* __restrict__ sums,
                           const float* __restrict__ counts,
                           float* __restrict__ out) {
    int i = blockIdx.x * blockDim.x + threadIdx.x;
    if (i < N_GRAPHS * D_H) out[i] = sums[i] / fmaxf(counts[i >> 8], 1.f);
}

// ==================== launch ====================
extern "C" void kernel_launch(void* const* d_in, const int* in_sizes, int n_in,
                              void* d_out, int out_size) {
    const float* x     = (const float*)d_in[0];
    const int*   ei    = (const int*)d_in[1];
    const int*   batch = (const int*)d_in[2];
    const float* W1_0 = (const float*)d_in[3];
    const float* b1_0 = (const float*)d_in[4];
    const float* W2_0 = (const float*)d_in[5];
    const float* b2_0 = (const float*)d_in[6];
    const float* W1_1 = (const float*)d_in[7];
    const float* b1_1 = (const float*)d_in[8];
    const float* W2_1 = (const float*)d_in[9];
    const float* b2_1 = (const float*)d_in[10];
    float* out = (float*)d_out;

    float *sums, *counts;
    __half *x16, *a16, *t16, *h16, *wh;
    int *cursor, *csr;
    cudaGetSymbolAddress((void**)&x16,    g_x16);
    cudaGetSymbolAddress((void**)&a16,    g_a16);
    cudaGetSymbolAddress((void**)&t16,    g_t16);
    cudaGetSymbolAddress((void**)&h16,    g_h16);
    cudaGetSymbolAddress((void**)&wh,     g_wh);
    cudaGetSymbolAddress((void**)&cursor, g_cursor);
    cudaGetSymbolAddress((void**)&csr,    g_csr);
    cudaGetSymbolAddress((void**)&sums,   g_sums);
    cudaGetSymbolAddress((void**)&counts, g_counts);
    __half* wh0 = wh;
    __half* wh1 = wh + D_H * D_H;
    __half* wh2 = wh + 2 * D_H * D_H;
    __half* wh3 = wh + 3 * D_H * D_H;

    cudaFuncSetAttribute(gemm_f16, cudaFuncAttributeMaxDynamicSharedMemorySize, GEMM_SMEM);

    const dim3 gemm_grid((N_NODES + 127) / 128, 2);
    const int  edge_blocks = (N_EDGES + 255) / 256;
    const int  node_warp_blocks = (N_NODES * 32 + 255) / 256;
    const int  init_threads = N_NODES * D_IN / 4;

    // ---- init + slotted CSR fill ----
    init_kernel<<<(init_threads + 255) / 256, 256>>>((const float4*)x, (uint2*)x16,
                                                     W1_0, W2_0, W1_1, W2_1, wh,
                                                     cursor, sums, counts);
    fill_kernel<<<edge_blocks, 256>>>(ei, cursor, csr);

    // ---- layer 0 ----
    gather_f16<D_IN><<<node_warp_blocks, 256>>>(x16, cursor, csr, a16);
    gemm_f16<<<gemm_grid, 256, GEMM_SMEM>>>(a16, wh0, b1_0, t16, N_NODES, D_IN);
    gemm_f16<<<gemm_grid, 256, GEMM_SMEM>>>(t16, wh1, b2_0, h16, N_NODES, D_H);

    // ---- layer 1 ----
    gather_f16<D_H><<<node_warp_blocks, 256>>>(h16, cursor, csr, a16);
    gemm_f16<<<gemm_grid, 256, GEMM_SMEM>>>(a16, wh2, b1_1, t16, N_NODES, D_H);
    gemm_f16<<<gemm_grid, 256, GEMM_SMEM>>>(t16, wh3, b2_1, h16, N_NODES, D_H);

    // ---- pool ----
    pool_kernel<<<(N_NODES + POOL_NPB - 1) / POOL_NPB, 256>>>(h16, batch, sums, counts);
    div_kernel<<<(N_GRAPHS * D_H + 255) / 256, 256>>>(sums, counts, out);
}